// round 9
// baseline (speedup 1.0000x reference)
#include <cuda_runtime.h>
#include <cuda_bf16.h>
#include <math.h>
#include <stdint.h>

#define B_  512
#define S_  512
#define DI_ 256
#define DO_ 256

// Packed Wh A-fragments (R5 layout): [g(=t*8+kh*4+c)][wm(8)][ks(4)][mt(2)][lane(32)] float4.
// 4096 * 8 * 4 * 2 * 32 = 8,388,608 float4 = 134 MB.
__device__ float4 WhP_g[(size_t)S_ * 8 * 8 * 4 * 2 * 32];

// ---------------- helpers ----------------

__device__ __forceinline__ void cpasync16(void* smem_dst, const void* gsrc) {
    unsigned saddr = (unsigned)__cvta_generic_to_shared(smem_dst);
    asm volatile("cp.async.cg.shared.global [%0], [%1], 16;\n" :: "r"(saddr), "l"(gsrc));
}
__device__ __forceinline__ void cp_commit() { asm volatile("cp.async.commit_group;\n"); }
template <int N> __device__ __forceinline__ void cp_wait() {
    asm volatile("cp.async.wait_group %0;\n" :: "n"(N));
}
__device__ __forceinline__ unsigned f2u(float f) { return __float_as_uint(f); }
__device__ __forceinline__ float fast_tanh(float x) {
    float e = __expf(2.0f * x);
    return 1.0f - __fdividef(2.0f, e + 1.0f);
}
__device__ __forceinline__ uint32_t smem_u32(const void* p) {
    return (uint32_t)__cvta_generic_to_shared(p);
}

__device__ __forceinline__ void mma_tf32(float c[4],
                                         unsigned a0, unsigned a1, unsigned a2, unsigned a3,
                                         unsigned b0, unsigned b1) {
    asm volatile(
        "mma.sync.aligned.m16n8k8.row.col.f32.tf32.tf32.f32 "
        "{%0,%1,%2,%3}, {%4,%5,%6,%7}, {%8,%9}, {%0,%1,%2,%3};\n"
        : "+f"(c[0]), "+f"(c[1]), "+f"(c[2]), "+f"(c[3])
        : "r"(a0), "r"(a1), "r"(a2), "r"(a3), "r"(b0), "r"(b1));
}

#define LDSM_X4(r0, r1, r2, r3, addr) \
    asm volatile("ldmatrix.sync.aligned.m8n8.x4.shared.b16 {%0,%1,%2,%3}, [%4];" \
                 : "=r"(r0), "=r"(r1), "=r"(r2), "=r"(r3) : "r"(addr))

// ---------------- Phase 0: pack Wh into fragment-major layout (R5 version, verbatim) ----------------

__global__ __launch_bounds__(256, 1) void prepack_wh(const float* __restrict__ Wh)
{
    __shared__ float tile[32 * 260];
    const int slab = blockIdx.x;
    const int t    = blockIdx.y;
    const int tid  = threadIdx.x;
    const float* src = Wh + (size_t)t * (DO_ * DO_) + (size_t)slab * 32 * DO_;

#pragma unroll
    for (int j = 0; j < 8; j++) {
        int idx = tid + j * 256;
        int r = idx >> 6, q = idx & 63;
        *(float4*)&tile[r * 260 + q * 4] = *(const float4*)&src[r * DO_ + q * 4];
    }
    __syncthreads();

    const size_t g = (size_t)t * 8 + slab;
#pragma unroll
    for (int j = 0; j < 8; j++) {
        int idx  = tid + j * 256;
        int lane = idx & 31;
        int mt   = (idx >> 5) & 1;
        int ks   = (idx >> 6) & 3;
        int wm   = (idx >> 8) & 7;
        int kloc = ks * 8 + (lane & 3);
        int m0   = wm * 32 + mt * 16 + (lane >> 2);
        float4 v;
        v.x = tile[kloc * 260 + m0];
        v.y = tile[kloc * 260 + m0 + 8];
        v.z = tile[(kloc + 4) * 260 + m0];
        v.w = tile[(kloc + 4) * 260 + m0 + 8];
        WhP_g[(g * 8 + wm) * 256 + (ks * 2 + mt) * 32 + lane] = v;
    }
}

// ---------------- Phase 1 v2: 256x128 tiles, 1 commit-group/chunk, wait<1> ----------------
// Grid (N/128=2, M/256=2, 512). 8 warps: wm = warp&3 (64 rows), wn = warp>>2 (64 cols).
// Warp tile 64x64: acc[4][8][4]. K=256 in 8 chunks of 32, double-buffered cp.async.

#define P1_AS  (256 * 36)
#define P1_BS  (32 * 132)
#define P1_SMEM ((2 * (P1_AS + P1_BS)) * 4)   // 107,520 B

__global__ __launch_bounds__(256, 1) void rnn_phase1(
    const float* __restrict__ x, const float* __restrict__ Wx, float* __restrict__ out)
{
    extern __shared__ float sm[];
    float* As[2] = { sm, sm + P1_AS };
    float* Bs[2] = { sm + 2 * P1_AS, sm + 2 * P1_AS + P1_BS };

    const int t      = blockIdx.z;
    const int m_base = blockIdx.y * 256;
    const int n_base = blockIdx.x * 128;
    const int tid    = threadIdx.x;
    const int warp   = tid >> 5, lane = tid & 31;
    const int wm     = warp & 3, wn = warp >> 2;
    const int grp    = lane >> 2, tig = lane & 3;

    float acc[4][8][4];
#pragma unroll
    for (int mt = 0; mt < 4; mt++)
#pragma unroll
        for (int nt = 0; nt < 8; nt++)
#pragma unroll
            for (int i = 0; i < 4; i++) acc[mt][nt][i] = 0.f;

    // one commit group per chunk: A (2048 f4) + B (1024 f4)
    auto loadChunk = [&](int kc, int buf) {
#pragma unroll
        for (int j = 0; j < 8; j++) {
            int i = tid + j * 256;
            int r = i >> 3, q = i & 7;           // r 0..255, q 0..7
            cpasync16(&As[buf][r * 36 + q * 4],
                      x + ((size_t)(m_base + r) * S_ + t) * DI_ + kc * 32 + q * 4);
        }
#pragma unroll
        for (int j = 0; j < 4; j++) {
            int i = tid + j * 256;
            int k = i >> 5, q = i & 31;          // k 0..31, q 0..31
            cpasync16(&Bs[buf][k * 132 + q * 4],
                      Wx + (size_t)t * (DI_ * DO_) + (size_t)(kc * 32 + k) * DO_ + n_base + q * 4);
        }
        cp_commit();
    };

    loadChunk(0, 0);
    loadChunk(1, 1);

    for (int kc = 0; kc < 8; kc++) {
        if (kc < 7) cp_wait<1>(); else cp_wait<0>();
        __syncthreads();
        const int buf = kc & 1;
        const float* A = As[buf];
        const float* Bsm = Bs[buf];
#pragma unroll
        for (int ks = 0; ks < 4; ks++) {
            const int k = ks * 8;
            unsigned a[4][4];
#pragma unroll
            for (int mt = 0; mt < 4; mt++) {
                const int rb = wm * 64 + mt * 16;
                a[mt][0] = f2u(A[(rb + grp)     * 36 + k + tig]);
                a[mt][1] = f2u(A[(rb + grp + 8) * 36 + k + tig]);
                a[mt][2] = f2u(A[(rb + grp)     * 36 + k + 4 + tig]);
                a[mt][3] = f2u(A[(rb + grp + 8) * 36 + k + 4 + tig]);
            }
#pragma unroll
            for (int nt = 0; nt < 8; nt++) {
                const int cb = wn * 64 + nt * 8 + grp;
                unsigned b0 = f2u(Bsm[(k + tig)     * 132 + cb]);
                unsigned b1 = f2u(Bsm[(k + 4 + tig) * 132 + cb]);
#pragma unroll
                for (int mt = 0; mt < 4; mt++)
                    mma_tf32(acc[mt][nt], a[mt][0], a[mt][1], a[mt][2], a[mt][3], b0, b1);
            }
        }
        __syncthreads();
        if (kc + 2 < 8) loadChunk(kc + 2, buf);
    }

#pragma unroll
    for (int mt = 0; mt < 4; mt++) {
#pragma unroll
        for (int nt = 0; nt < 8; nt++) {
            const int row = m_base + wm * 64 + mt * 16 + grp;
            const int col = n_base + wn * 64 + nt * 8 + 2 * tig;
            const size_t g0 = ((size_t)row * S_ + t) * DO_ + col;
            float2 v0; v0.x = acc[mt][nt][0]; v0.y = acc[mt][nt][1];
            *(float2*)&out[g0] = v0;
            const size_t g1 = ((size_t)(row + 8) * S_ + t) * DO_ + col;
            float2 v1; v1.x = acc[mt][nt][2]; v1.y = acc[mt][nt][3];
            *(float2*)&out[g1] = v1;
        }
    }
}

// ---------------- Phase 2 (R5 verbatim — best measured): 64 CTAs x 512 thr, k-split ----------------

#define P2_HPAD 260

__global__ __launch_bounds__(512, 1) void rnn_phase2(float* __restrict__ out)
{
    __shared__ __align__(16) float hs[8 * P2_HPAD];
    __shared__ __align__(16) float4 scr[2][8][32];

    const int tid  = threadIdx.x;
    const int w    = tid >> 5, lane = tid & 31;
    const int grp  = lane >> 2, tig = lane & 3;
    const int kh   = w >> 3, wm = w & 7;
    const int brow = blockIdx.x * 8;
    const int m0   = wm * 32 + kh * 16 + grp;
    const int n0   = 2 * tig;

    for (int i = tid; i < 8 * P2_HPAD; i += 512) hs[i] = 0.f;
    __syncthreads();

    const uint32_t hs_base = smem_u32(hs);
    const uint32_t lm_row  = (uint32_t)((lane & 7) * P2_HPAD + (lane >> 3) * 4) * 4;

    float4 A[2][4][2];

    auto ldA = [&](int s, int st) {
        const int g = ((s >> 2) << 3) | (kh << 2) | (s & 3);
        const size_t base = ((size_t)g * 8 + wm) * 256 + lane;
#pragma unroll
        for (int ks = 0; ks < 4; ks++)
#pragma unroll
            for (int mt = 0; mt < 2; mt++)
                A[st][ks][mt] = __ldg(&WhP_g[base + (ks * 2 + mt) * 32]);
    };

    ldA(0, 0);
    ldA(1, 1);

    float acc[2][4];
    float z[4];
    int s = 0;

    for (int t = 0; t < S_; t++) {
#pragma unroll
        for (int mt = 0; mt < 2; mt++)
#pragma unroll
            for (int i = 0; i < 4; i++) acc[mt][i] = 0.f;

        z[0] = __ldg(&out[((size_t)(brow + n0)     * S_ + t) * DO_ + m0]);
        z[1] = __ldg(&out[((size_t)(brow + n0 + 1) * S_ + t) * DO_ + m0]);
        z[2] = __ldg(&out[((size_t)(brow + n0)     * S_ + t) * DO_ + m0 + 8]);
        z[3] = __ldg(&out[((size_t)(brow + n0 + 1) * S_ + t) * DO_ + m0 + 8]);

        for (int c = 0; c < 4; c++) {
            const int st = s & 1;
            const int kb = kh * 128 + c * 32;
            const uint32_t a0 = hs_base + lm_row + (uint32_t)kb * 4;
            uint32_t b0, b1, b2, b3, b4, b5, b6, b7;
            LDSM_X4(b0, b1, b2, b3, a0);
            LDSM_X4(b4, b5, b6, b7, a0 + 64);

            const uint32_t bb[8] = { b0, b1, b2, b3, b4, b5, b6, b7 };
#pragma unroll
            for (int ks = 0; ks < 4; ks++) {
#pragma unroll
                for (int mt = 0; mt < 2; mt++) {
                    const float4 af = A[st][ks][mt];
                    mma_tf32(acc[mt], f2u(af.x), f2u(af.y), f2u(af.z), f2u(af.w),
                             bb[2 * ks], bb[2 * ks + 1]);
                }
            }
            if (s + 2 < 4 * S_) ldA(s + 2, st);
            s++;
        }

        if (kh == 0) {
            scr[0][wm][lane] = make_float4(acc[1][0], acc[1][1], acc[1][2], acc[1][3]);
        } else {
            scr[1][wm][lane] = make_float4(acc[0][0], acc[0][1], acc[0][2], acc[0][3]);
        }
        __syncthreads();

        const float4 p = scr[kh ^ 1][wm][lane];
        const float h0 = fast_tanh(z[0] + acc[kh][0] + p.x);
        const float h1 = fast_tanh(z[1] + acc[kh][1] + p.y);
        const float h2 = fast_tanh(z[2] + acc[kh][2] + p.z);
        const float h3 = fast_tanh(z[3] + acc[kh][3] + p.w);

        out[((size_t)(brow + n0)     * S_ + t) * DO_ + m0]     = h0;
        out[((size_t)(brow + n0 + 1) * S_ + t) * DO_ + m0]     = h1;
        out[((size_t)(brow + n0)     * S_ + t) * DO_ + m0 + 8] = h2;
        out[((size_t)(brow + n0 + 1) * S_ + t) * DO_ + m0 + 8] = h3;

        hs[n0 * P2_HPAD + m0]           = h0;
        hs[(n0 + 1) * P2_HPAD + m0]     = h1;
        hs[n0 * P2_HPAD + m0 + 8]       = h2;
        hs[(n0 + 1) * P2_HPAD + m0 + 8] = h3;

        __syncthreads();
    }
}

// ---------------- launch ----------------

extern "C" void kernel_launch(void* const* d_in, const int* in_sizes, int n_in,
                              void* d_out, int out_size)
{
    const float* x  = (const float*)d_in[0];   // [B, S, DI]
    const float* Wx = (const float*)d_in[1];   // [S, DI, DO]
    const float* Wh = (const float*)d_in[2];   // [S, DO, DO]
    float* out = (float*)d_out;                // [B, S, DO]

    cudaFuncSetAttribute(rnn_phase1, cudaFuncAttributeMaxDynamicSharedMemorySize, P1_SMEM);

    prepack_wh<<<dim3(8, S_), 256>>>(Wh);

    dim3 g1(DO_ / 128, B_ / 256, S_);
    rnn_phase1<<<g1, 256, P1_SMEM>>>(x, Wx, out);

    rnn_phase2<<<B_ / 8, 512>>>(out);
}

// round 10
// speedup vs baseline: 2.0807x; 2.0807x over previous
#include <cuda_runtime.h>
#include <cuda_bf16.h>
#include <cuda_fp16.h>
#include <math.h>
#include <stdint.h>

#define B_  512
#define S_  512
#define DI_ 256
#define DO_ 256

// fp16-packed Wh A-fragments: [g(=t*8+kh*4+c)][wm(8)][s2(2)][mt(2)][lane(32)] float4(=8 f16).
// 4096 * 8 * 128 = 4,194,304 float4 = 67 MB.
__device__ float4 WhP_h[(size_t)S_ * 8 * 8 * 128];

// ---------------- helpers ----------------

__device__ __forceinline__ void cpasync16(void* smem_dst, const void* gsrc) {
    unsigned saddr = (unsigned)__cvta_generic_to_shared(smem_dst);
    asm volatile("cp.async.cg.shared.global [%0], [%1], 16;\n" :: "r"(saddr), "l"(gsrc));
}
__device__ __forceinline__ void cp_commit() { asm volatile("cp.async.commit_group;\n"); }
template <int N> __device__ __forceinline__ void cp_wait() {
    asm volatile("cp.async.wait_group %0;\n" :: "n"(N));
}
__device__ __forceinline__ unsigned f2u(float f) { return __float_as_uint(f); }
__device__ __forceinline__ float fast_tanh(float x) {
    float e = __expf(2.0f * x);
    return 1.0f - __fdividef(2.0f, e + 1.0f);
}
__device__ __forceinline__ uint32_t smem_u32(const void* p) {
    return (uint32_t)__cvta_generic_to_shared(p);
}
__device__ __forceinline__ uint32_t packh2(float a, float b) {
    __half2 h = __floats2half2_rn(a, b);   // .x = a (low 16 bits)
    return *(uint32_t*)&h;
}

// tf32 warp mma (phase 1)
__device__ __forceinline__ void mma_tf32(float c[4],
                                         unsigned a0, unsigned a1, unsigned a2, unsigned a3,
                                         unsigned b0, unsigned b1) {
    asm volatile(
        "mma.sync.aligned.m16n8k8.row.col.f32.tf32.tf32.f32 "
        "{%0,%1,%2,%3}, {%4,%5,%6,%7}, {%8,%9}, {%0,%1,%2,%3};\n"
        : "+f"(c[0]), "+f"(c[1]), "+f"(c[2]), "+f"(c[3])
        : "r"(a0), "r"(a1), "r"(a2), "r"(a3), "r"(b0), "r"(b1));
}

// fp16 warp mma, fp32 accum (phase 2)
__device__ __forceinline__ void mma_f16(float c[4],
                                        unsigned a0, unsigned a1, unsigned a2, unsigned a3,
                                        unsigned b0, unsigned b1) {
    asm volatile(
        "mma.sync.aligned.m16n8k16.row.col.f32.f16.f16.f32 "
        "{%0,%1,%2,%3}, {%4,%5,%6,%7}, {%8,%9}, {%0,%1,%2,%3};\n"
        : "+f"(c[0]), "+f"(c[1]), "+f"(c[2]), "+f"(c[3])
        : "r"(a0), "r"(a1), "r"(a2), "r"(a3), "r"(b0), "r"(b1));
}

#define LDSM_X4(r0, r1, r2, r3, addr) \
    asm volatile("ldmatrix.sync.aligned.m8n8.x4.shared.b16 {%0,%1,%2,%3}, [%4];" \
                 : "=r"(r0), "=r"(r1), "=r"(r2), "=r"(r3) : "r"(addr))

// ---------------- Phase 0: pack Wh -> fp16 fragments ----------------
// grid (slab=8, t=512), 256 thr; slab covers k rows [slab*32, +32) (slab = kh*4 + c).
// A = Wh^T: A[m][k] = Wh[k][m] = tile[kloc][m].
// Element [wm][s2][mt][lane]: r=lane>>2, cc=(lane&3)*2, m0=wm*32+mt*16+r, kk=s2*16+cc:
//   x = h2(A[m0][kk],   A[m0][kk+1])    y = h2(A[m0+8][kk],   A[m0+8][kk+1])
//   z = h2(A[m0][kk+8], A[m0][kk+9])    w = h2(A[m0+8][kk+8], A[m0+8][kk+9])

__global__ __launch_bounds__(256, 1) void prepack_wh(const float* __restrict__ Wh)
{
    __shared__ float tile[32 * 260];
    const int slab = blockIdx.x;
    const int t    = blockIdx.y;
    const int tid  = threadIdx.x;
    const float* src = Wh + (size_t)t * (DO_ * DO_) + (size_t)slab * 32 * DO_;

#pragma unroll
    for (int j = 0; j < 8; j++) {
        int idx = tid + j * 256;
        int r = idx >> 6, q = idx & 63;
        *(float4*)&tile[r * 260 + q * 4] = *(const float4*)&src[r * DO_ + q * 4];
    }
    __syncthreads();

    const size_t g = (size_t)t * 8 + slab;
#pragma unroll
    for (int j = 0; j < 4; j++) {
        int idx  = tid + j * 256;               // 0..1023
        int lane = idx & 31;
        int mt   = (idx >> 5) & 1;
        int s2   = (idx >> 6) & 1;
        int wm   = (idx >> 7) & 7;
        int r    = lane >> 2, cc = (lane & 3) * 2;
        int m0   = wm * 32 + mt * 16 + r;
        int kk   = s2 * 16 + cc;
        float4 v;
        v.x = __uint_as_float(packh2(tile[kk * 260 + m0],       tile[(kk + 1) * 260 + m0]));
        v.y = __uint_as_float(packh2(tile[kk * 260 + m0 + 8],   tile[(kk + 1) * 260 + m0 + 8]));
        v.z = __uint_as_float(packh2(tile[(kk + 8) * 260 + m0], tile[(kk + 9) * 260 + m0]));
        v.w = __uint_as_float(packh2(tile[(kk + 8) * 260 + m0 + 8], tile[(kk + 9) * 260 + m0 + 8]));
        WhP_h[(g * 8 + wm) * 128 + (s2 * 2 + mt) * 32 + lane] = v;
    }
}

// ---------------- Phase 1: Z = x @ Wx (R5 verbatim — tf32, 128x128, 2 CTAs/SM) ----------------

#define P1_AS  (128 * 36)
#define P1_BS  (32 * 132)
#define P1_SMEM ((2 * P1_AS + 2 * P1_BS) * 4)

__global__ __launch_bounds__(256, 2) void rnn_phase1(
    const float* __restrict__ x, const float* __restrict__ Wx, float* __restrict__ out)
{
    extern __shared__ float sm[];
    float* As[2] = { sm, sm + P1_AS };
    float* Bs[2] = { sm + 2 * P1_AS, sm + 2 * P1_AS + P1_BS };

    const int t      = blockIdx.z;
    const int m_base = blockIdx.y * 128;
    const int n_base = blockIdx.x * 128;
    const int tid    = threadIdx.x;
    const int warp   = tid >> 5, lane = tid & 31;
    const int wm     = warp & 3, wn = warp >> 2;
    const int grp    = lane >> 2, tig = lane & 3;

    float acc[2][8][4];
#pragma unroll
    for (int mt = 0; mt < 2; mt++)
#pragma unroll
        for (int nt = 0; nt < 8; nt++)
#pragma unroll
            for (int i = 0; i < 4; i++) acc[mt][nt][i] = 0.f;

    auto loadA = [&](int kc, int buf) {
#pragma unroll
        for (int j = 0; j < 4; j++) {
            int i = tid + j * 256;
            int r = i >> 3, q = i & 7;
            cpasync16(&As[buf][r * 36 + q * 4],
                      x + ((m_base + r) * S_ + t) * DI_ + kc * 32 + q * 4);
        }
        cp_commit();
    };
    auto loadB = [&](int kc, int buf) {
#pragma unroll
        for (int j = 0; j < 4; j++) {
            int i = tid + j * 256;
            int k = i >> 5, q = i & 31;
            cpasync16(&Bs[buf][k * 132 + q * 4],
                      Wx + t * (DI_ * DO_) + (kc * 32 + k) * DO_ + n_base + q * 4);
        }
        cp_commit();
    };

    loadA(0, 0); loadB(0, 0);
    loadA(1, 1); loadB(1, 1);

    for (int kc = 0; kc < 8; kc++) {
        if (kc < 7) cp_wait<2>(); else cp_wait<0>();
        __syncthreads();
        const int buf = kc & 1;
        const float* A = As[buf];
        const float* Bsm = Bs[buf];
#pragma unroll
        for (int ks = 0; ks < 4; ks++) {
            const int k = ks * 8;
            unsigned a[2][4];
#pragma unroll
            for (int mt = 0; mt < 2; mt++) {
                const int rb = wm * 32 + mt * 16;
                a[mt][0] = f2u(A[(rb + grp)     * 36 + k + tig]);
                a[mt][1] = f2u(A[(rb + grp + 8) * 36 + k + tig]);
                a[mt][2] = f2u(A[(rb + grp)     * 36 + k + 4 + tig]);
                a[mt][3] = f2u(A[(rb + grp + 8) * 36 + k + 4 + tig]);
            }
#pragma unroll
            for (int nt = 0; nt < 8; nt++) {
                const int cb = wn * 64 + nt * 8 + grp;
                unsigned b0 = f2u(Bsm[(k + tig)     * 132 + cb]);
                unsigned b1 = f2u(Bsm[(k + 4 + tig) * 132 + cb]);
#pragma unroll
                for (int mt = 0; mt < 2; mt++)
                    mma_tf32(acc[mt][nt], a[mt][0], a[mt][1], a[mt][2], a[mt][3], b0, b1);
            }
        }
        __syncthreads();
        if (kc + 2 < 8) { loadA(kc + 2, buf); loadB(kc + 2, buf); }
    }

#pragma unroll
    for (int mt = 0; mt < 2; mt++) {
#pragma unroll
        for (int nt = 0; nt < 8; nt++) {
            const int row = m_base + wm * 32 + mt * 16 + grp;
            const int col = n_base + wn * 64 + nt * 8 + 2 * tig;
            const int g0 = (row * S_ + t) * DO_ + col;
            float2 v0; v0.x = acc[mt][nt][0]; v0.y = acc[mt][nt][1];
            *(float2*)&out[g0] = v0;
            const int g1 = ((row + 8) * S_ + t) * DO_ + col;
            float2 v1; v1.x = acc[mt][nt][2]; v1.y = acc[mt][nt][3];
            *(float2*)&out[g1] = v1;
        }
    }
}

// ---------------- Phase 2 (fp16): 64 CTAs x 512 thr, k-split, m16n8k16 ----------------
// R5 structure; Wh and h in fp16 (same 10-bit mantissa as tf32 -> identical error).
// Per warp per chunk (k32): 1 ldmatrix.x4 (B) + 4 LDG.128 (A) + 4 mma (was 2+8+8).

#define P2_HSTR 264   // fp16 h row stride (264 halfs = 528B; rows land on distinct bank groups)

__global__ __launch_bounds__(512, 1) void rnn_phase2(float* __restrict__ out)
{
    __shared__ __align__(16) __half hs2[8 * P2_HSTR];
    __shared__ __align__(16) float4 scr[2][8][32];

    const int tid  = threadIdx.x;
    const int w    = tid >> 5, lane = tid & 31;
    const int grp  = lane >> 2, tig = lane & 3;
    const int kh   = w >> 3, wm = w & 7;
    const int brow = blockIdx.x * 8;
    const int m0   = wm * 32 + kh * 16 + grp;   // epilogue col base (own mt=kh tile)
    const int n0   = 2 * tig;

    for (int i = tid; i < 8 * P2_HSTR / 2; i += 512) ((uint32_t*)hs2)[i] = 0u;
    __syncthreads();

    const uint32_t hs_base = smem_u32(hs2);
    // ldmatrix.x4 lane row addr: row n=(lane&7), k-block (lane>>3)*8 halfs = *16B
    const uint32_t lmb = hs_base + (uint32_t)(lane & 7) * (P2_HSTR * 2) + (uint32_t)(lane >> 3) * 16;

    float4 A[2][2][2];   // [stage][s2][mt]

    auto ldA = [&](int s, int st) {
        const int g = ((s >> 2) << 3) | (kh << 2) | (s & 3);
        const size_t base = ((size_t)g * 8 + wm) * 128 + lane;
        A[st][0][0] = __ldg(&WhP_h[base]);
        A[st][0][1] = __ldg(&WhP_h[base + 32]);
        A[st][1][0] = __ldg(&WhP_h[base + 64]);
        A[st][1][1] = __ldg(&WhP_h[base + 96]);
    };

    ldA(0, 0);
    ldA(1, 1);

    float acc[2][4];
    float z[4];
    int s = 0;

    for (int t = 0; t < S_; t++) {
#pragma unroll
        for (int mt = 0; mt < 2; mt++)
#pragma unroll
            for (int i = 0; i < 4; i++) acc[mt][i] = 0.f;

        // Z prefetch (independent of h)
        z[0] = __ldg(&out[((size_t)(brow + n0)     * S_ + t) * DO_ + m0]);
        z[1] = __ldg(&out[((size_t)(brow + n0 + 1) * S_ + t) * DO_ + m0]);
        z[2] = __ldg(&out[((size_t)(brow + n0)     * S_ + t) * DO_ + m0 + 8]);
        z[3] = __ldg(&out[((size_t)(brow + n0 + 1) * S_ + t) * DO_ + m0 + 8]);

        for (int c = 0; c < 4; c++) {
            const int st = s & 1;
            const int k0 = kh * 128 + c * 32;
            uint32_t b0, b1, b2, b3;
            LDSM_X4(b0, b1, b2, b3, lmb + (uint32_t)k0 * 2);

            // s2 = 0 (k0..k15)
            {
                const float4 af0 = A[st][0][0];
                mma_f16(acc[0], f2u(af0.x), f2u(af0.y), f2u(af0.z), f2u(af0.w), b0, b1);
                const float4 af1 = A[st][0][1];
                mma_f16(acc[1], f2u(af1.x), f2u(af1.y), f2u(af1.z), f2u(af1.w), b0, b1);
            }
            // s2 = 1 (k16..k31)
            {
                const float4 af0 = A[st][1][0];
                mma_f16(acc[0], f2u(af0.x), f2u(af0.y), f2u(af0.z), f2u(af0.w), b2, b3);
                const float4 af1 = A[st][1][1];
                mma_f16(acc[1], f2u(af1.x), f2u(af1.y), f2u(af1.z), f2u(af1.w), b2, b3);
            }

            if (s + 2 < 4 * S_) ldA(s + 2, st);
            s++;
        }

        // exchange partial sums for the other mt tile
        if (kh == 0) {
            scr[0][wm][lane] = make_float4(acc[1][0], acc[1][1], acc[1][2], acc[1][3]);
        } else {
            scr[1][wm][lane] = make_float4(acc[0][0], acc[0][1], acc[0][2], acc[0][3]);
        }
        __syncthreads();

        const float4 p = scr[kh ^ 1][wm][lane];
        const float h0 = fast_tanh(z[0] + acc[kh][0] + p.x);
        const float h1 = fast_tanh(z[1] + acc[kh][1] + p.y);
        const float h2 = fast_tanh(z[2] + acc[kh][2] + p.z);
        const float h3 = fast_tanh(z[3] + acc[kh][3] + p.w);

        out[((size_t)(brow + n0)     * S_ + t) * DO_ + m0]     = h0;
        out[((size_t)(brow + n0 + 1) * S_ + t) * DO_ + m0]     = h1;
        out[((size_t)(brow + n0)     * S_ + t) * DO_ + m0 + 8] = h2;
        out[((size_t)(brow + n0 + 1) * S_ + t) * DO_ + m0 + 8] = h3;

        hs2[n0 * P2_HSTR + m0]           = __float2half_rn(h0);
        hs2[(n0 + 1) * P2_HSTR + m0]     = __float2half_rn(h1);
        hs2[n0 * P2_HSTR + m0 + 8]       = __float2half_rn(h2);
        hs2[(n0 + 1) * P2_HSTR + m0 + 8] = __float2half_rn(h3);

        __syncthreads();
    }
}

// ---------------- launch ----------------

extern "C" void kernel_launch(void* const* d_in, const int* in_sizes, int n_in,
                              void* d_out, int out_size)
{
    const float* x  = (const float*)d_in[0];   // [B, S, DI]
    const float* Wx = (const float*)d_in[1];   // [S, DI, DO]
    const float* Wh = (const float*)d_in[2];   // [S, DO, DO]
    float* out = (float*)d_out;                // [B, S, DO]

    cudaFuncSetAttribute(rnn_phase1, cudaFuncAttributeMaxDynamicSharedMemorySize, P1_SMEM);

    prepack_wh<<<dim3(8, S_), 256>>>(Wh);

    dim3 g1(DO_ / 128, B_ / 128, S_);
    rnn_phase1<<<g1, 256, P1_SMEM>>>(x, Wx, out);

    rnn_phase2<<<B_ / 8, 512>>>(out);
}